// round 1
// baseline (speedup 1.0000x reference)
#include <cuda_runtime.h>
#include <math.h>

#define NN 100000
#define NE 1600000
#define SD 64
#define VD 64
#define HID 128
#define INP 196           // 195 real + 1 zero-padded row
#define TILE 64
#define STRA 68           // A/H row stride (floats), breaks bank conflicts, keeps float4 align
#define NT ((NE + TILE - 1) / TILE)

// dynamic smem layout (floats):
//   W1s : INP*HID            = 25088
//   W2s : HID*HID            = 16384
//   A   : INP*STRA           = 13328   (aliased by H[128][STRA] in layer 2)
//   dstS: 64 ints
#define SMEM_FLOATS (INP*HID + HID*HID + INP*STRA)
#define SMEM_BYTES  (SMEM_FLOATS*4 + TILE*4)

__device__ __forceinline__ void red_add_v4(float* a, float x, float y, float z, float w) {
    asm volatile("red.global.add.v4.f32 [%0], {%1,%2,%3,%4};"
                 :: "l"(a), "f"(x), "f"(y), "f"(z), "f"(w) : "memory");
}

__global__ void init_out_kernel(const float* __restrict__ hs,
                                const float* __restrict__ hv,
                                float* __restrict__ out) {
    size_t i = (size_t)blockIdx.x * blockDim.x + threadIdx.x;
    const size_t n4 = (size_t)NN * SD / 4;   // 1.6M float4 per half
    const float4* hs4 = (const float4*)hs;
    const float4* hv4 = (const float4*)hv;
    float4* o4 = (float4*)out;
    if (i < n4) {
        o4[i]      = hs4[i];
        o4[n4 + i] = hv4[i];
    }
}

extern __shared__ float sm[];

__global__ void __launch_bounds__(256, 1)
edge_kernel(const float* __restrict__ h_s, const float* __restrict__ h_v,
            const float* __restrict__ pos, const float* __restrict__ orient,
            const float* __restrict__ W1,  const float* __restrict__ b1,
            const float* __restrict__ W2,  const float* __restrict__ b2,
            const int*   __restrict__ ei,  float* __restrict__ out) {
    float* W1s = sm;                       // [INP][HID]
    float* W2s = sm + INP * HID;           // [HID][HID]
    float* A   = W2s + HID * HID;          // [INP][STRA], reused as H[HID][STRA]
    int*  dstS = (int*)(A + INP * STRA);   // [TILE]

    const int tid = threadIdx.x;
    const int tx = tid & 15;               // output group: t in [tx*8, tx*8+8)
    const int ty = tid >> 4;               // edge group:   e in [ty*4, ty*4+4)

    // ---- load weights into SMEM once per block (persistent blocks) ----
    {
        const float4* g1 = (const float4*)W1;
        float4* s1 = (float4*)W1s;
        for (int i = tid; i < (195 * HID) / 4; i += 256) s1[i] = g1[i];
        float4 z4 = make_float4(0.f, 0.f, 0.f, 0.f);
        for (int i = tid; i < HID / 4; i += 256)
            ((float4*)(W1s + 195 * HID))[i] = z4;       // padded row 195 = 0
        const float4* g2 = (const float4*)W2;
        float4* s2 = (float4*)W2s;
        for (int i = tid; i < (HID * HID) / 4; i += 256) s2[i] = g2[i];
    }
    float b1r[8], b2r[8];
    #pragma unroll
    for (int j = 0; j < 8; j++) { b1r[j] = b1[tx * 8 + j]; b2r[j] = b2[tx * 8 + j]; }

    const int e = tid >> 2;                // 0..63: which edge this thread builds
    const int p = tid & 3;                 // which quarter of the input vector

    const float* Acol = A + ty * 4;
    const float* Wcol1 = W1s + tx * 8;
    const float* Wcol2 = W2s + tx * 8;

    for (int tile = blockIdx.x; tile < NT; tile += gridDim.x) {
        __syncthreads();   // protect A/H + dstS reuse across tiles

        // ---- build message-input tile A[196][64] ----
        {
            int ge = tile * TILE + e;
            bool valid = ge < NE;
            int src = valid ? ei[ge] : 0;
            int dst = valid ? ei[NE + ge] : 0;
            if (p == 0) {                  // rows 0..63: h_s[src]
                const float4* r = (const float4*)(h_s + (size_t)src * SD);
                #pragma unroll
                for (int j = 0; j < 16; j++) {
                    float4 v = r[j];
                    A[(4*j+0)*STRA + e] = v.x;
                    A[(4*j+1)*STRA + e] = v.y;
                    A[(4*j+2)*STRA + e] = v.z;
                    A[(4*j+3)*STRA + e] = v.w;
                }
            } else if (p == 1) {           // rows 64..127: h_s[dst]
                const float4* r = (const float4*)(h_s + (size_t)dst * SD);
                #pragma unroll
                for (int j = 0; j < 16; j++) {
                    float4 v = r[j];
                    A[(64+4*j+0)*STRA + e] = v.x;
                    A[(64+4*j+1)*STRA + e] = v.y;
                    A[(64+4*j+2)*STRA + e] = v.z;
                    A[(64+4*j+3)*STRA + e] = v.w;
                }
            } else if (p == 2) {           // rows 128..191: rotated h_v[src]
                float alpha = orient[dst];
                float beta  = orient[src];
                float c, s_;
                sincosf(2.f * (beta - alpha), &s_, &c);
                const float4* r = (const float4*)(h_v + (size_t)src * VD);
                #pragma unroll
                for (int j = 0; j < 16; j++) {
                    float4 v = r[j];
                    A[(128+4*j+0)*STRA + e] = v.x * c - v.y * s_;
                    A[(128+4*j+1)*STRA + e] = v.x * s_ + v.y * c;
                    A[(128+4*j+2)*STRA + e] = v.z * c - v.w * s_;
                    A[(128+4*j+3)*STRA + e] = v.z * s_ + v.w * c;
                }
            } else {                       // rows 192..195: geo features + pad
                float2 ps = ((const float2*)pos)[src];
                float2 pd = ((const float2*)pos)[dst];
                float dx = ps.x - pd.x, dy = ps.y - pd.y;
                float dist = sqrtf(dx * dx + dy * dy) + 1e-6f;
                float alpha = orient[dst];
                float dphi = atan2f(dy, dx) - alpha;
                float c2, s2;
                sincosf(2.f * dphi, &s2, &c2);
                A[192*STRA + e] = dist;
                A[193*STRA + e] = c2;
                A[194*STRA + e] = s2;
                A[195*STRA + e] = 0.f;
                dstS[e] = valid ? dst : -1;
            }
        }
        __syncthreads();

        // ---- layer 1: [64e x 196] @ [196 x 128] ----
        float acc[4][8];
        #pragma unroll
        for (int i = 0; i < 4; i++)
            #pragma unroll
            for (int j = 0; j < 8; j++) acc[i][j] = b1r[j];

        #pragma unroll 4
        for (int k = 0; k < INP; k++) {
            float4 a  = *(const float4*)(Acol + k * STRA);
            float4 w0 = *(const float4*)(Wcol1 + k * HID);
            float4 w1v = *(const float4*)(Wcol1 + k * HID + 4);
            float av[4] = {a.x, a.y, a.z, a.w};
            float wv[8] = {w0.x, w0.y, w0.z, w0.w, w1v.x, w1v.y, w1v.z, w1v.w};
            #pragma unroll
            for (int i = 0; i < 4; i++)
                #pragma unroll
                for (int j = 0; j < 8; j++)
                    acc[i][j] = fmaf(av[i], wv[j], acc[i][j]);
        }
        __syncthreads();   // all reads of A done before H overwrites it

        // ---- SiLU, store H[128][STRA] into A's buffer ----
        #pragma unroll
        for (int j = 0; j < 8; j++) {
            float4 h4;
            float x;
            x = acc[0][j]; h4.x = x * (1.f / (1.f + __expf(-x)));
            x = acc[1][j]; h4.y = x * (1.f / (1.f + __expf(-x)));
            x = acc[2][j]; h4.z = x * (1.f / (1.f + __expf(-x)));
            x = acc[3][j]; h4.w = x * (1.f / (1.f + __expf(-x)));
            *(float4*)(A + (tx * 8 + j) * STRA + ty * 4) = h4;
        }
        __syncthreads();

        // ---- layer 2: [64e x 128] @ [128 x 128] ----
        float acc2[4][8];
        #pragma unroll
        for (int i = 0; i < 4; i++)
            #pragma unroll
            for (int j = 0; j < 8; j++) acc2[i][j] = b2r[j];

        #pragma unroll 4
        for (int k = 0; k < HID; k++) {
            float4 a  = *(const float4*)(Acol + k * STRA);
            float4 w0 = *(const float4*)(Wcol2 + k * HID);
            float4 w1v = *(const float4*)(Wcol2 + k * HID + 4);
            float av[4] = {a.x, a.y, a.z, a.w};
            float wv[8] = {w0.x, w0.y, w0.z, w0.w, w1v.x, w1v.y, w1v.z, w1v.w};
            #pragma unroll
            for (int i = 0; i < 4; i++)
                #pragma unroll
                for (int j = 0; j < 8; j++)
                    acc2[i][j] = fmaf(av[i], wv[j], acc2[i][j]);
        }

        // ---- scatter-add: msg_s -> out[0:NN*64), msg_v -> out[NN*64:) ----
        const size_t outv_off = (size_t)NN * SD;
        #pragma unroll
        for (int i = 0; i < 4; i++) {
            int d = dstS[ty * 4 + i];
            if (d >= 0) {
                float* base = (tx < 8)
                    ? out + (size_t)d * SD + tx * 8
                    : out + outv_off + (size_t)d * VD + (tx - 8) * 8;
                red_add_v4(base,     acc2[i][0], acc2[i][1], acc2[i][2], acc2[i][3]);
                red_add_v4(base + 4, acc2[i][4], acc2[i][5], acc2[i][6], acc2[i][7]);
            }
        }
    }
}

extern "C" void kernel_launch(void* const* d_in, const int* in_sizes, int n_in,
                              void* d_out, int out_size) {
    const float* h_s    = (const float*)d_in[0];
    const float* h_v    = (const float*)d_in[1];
    const float* pos    = (const float*)d_in[2];
    const float* orient = (const float*)d_in[3];
    const float* W1     = (const float*)d_in[4];
    const float* b1     = (const float*)d_in[5];
    const float* W2     = (const float*)d_in[6];
    const float* b2     = (const float*)d_in[7];
    const int*   ei     = (const int*)d_in[8];
    float* out = (float*)d_out;

    (void)in_sizes; (void)n_in; (void)out_size;

    // init out = [h_s | h_v]
    int n4 = NN * SD / 4;
    init_out_kernel<<<(n4 + 255) / 256, 256>>>(h_s, h_v, out);

    // fused edge MLP + scatter, persistent blocks (1 per SM)
    cudaFuncSetAttribute(edge_kernel,
                         cudaFuncAttributeMaxDynamicSharedMemorySize, SMEM_BYTES);
    int nsm = 148;
    cudaDeviceGetAttribute(&nsm, cudaDevAttrMultiProcessorCount, 0);
    edge_kernel<<<nsm, 256, SMEM_BYTES>>>(h_s, h_v, pos, orient,
                                          W1, b1, W2, b2, ei, out);
}

// round 2
// speedup vs baseline: 1.1953x; 1.1953x over previous
#include <cuda_runtime.h>
#include <math.h>

#define NN 100000
#define NE 1600000
#define SD 64
#define VD 64
#define HID 128
#define INP 196           // 195 real + 1 zero-padded row
#define TILE 64
#define STRA 68           // A/H row stride (floats); 272B, 16B-aligned
#define NT ((NE + TILE - 1) / TILE)
#define NTHREADS 128

// dynamic smem (floats): W1s INP*HID + W2s HID*HID + A INP*STRA (+64 ints)
#define SMEM_FLOATS (INP*HID + HID*HID + INP*STRA)
#define SMEM_BYTES  (SMEM_FLOATS*4 + TILE*4)

typedef unsigned long long u64;

#define FMA2(d, a, b) \
    asm("fma.rn.f32x2 %0, %1, %2, %0;" : "+l"(d) : "l"(a), "l"(b))
#define PACK2(d, f) \
    asm("mov.b64 %0, {%1, %1};" : "=l"(d) : "f"(f))
#define UNPACK2(lo, hi, v) \
    asm("mov.b64 {%0, %1}, %2;" : "=f"(lo), "=f"(hi) : "l"(v))

__device__ __forceinline__ void red_add_v4(float* a, float x, float y, float z, float w) {
    asm volatile("red.global.add.v4.f32 [%0], {%1,%2,%3,%4};"
                 :: "l"(a), "f"(x), "f"(y), "f"(z), "f"(w) : "memory");
}

__device__ __forceinline__ float silu(float x) {
    return x * (1.f / (1.f + __expf(-x)));
}

__global__ void init_out_kernel(const float* __restrict__ hs,
                                const float* __restrict__ hv,
                                float* __restrict__ out) {
    size_t i = (size_t)blockIdx.x * blockDim.x + threadIdx.x;
    const size_t n4 = (size_t)NN * SD / 4;
    const float4* hs4 = (const float4*)hs;
    const float4* hv4 = (const float4*)hv;
    float4* o4 = (float4*)out;
    if (i < n4) {
        o4[i]      = hs4[i];
        o4[n4 + i] = hv4[i];
    }
}

extern __shared__ float sm[];

__global__ void __launch_bounds__(NTHREADS, 1)
edge_kernel(const float* __restrict__ h_s, const float* __restrict__ h_v,
            const float* __restrict__ pos, const float* __restrict__ orient,
            const float* __restrict__ W1,  const float* __restrict__ b1,
            const float* __restrict__ W2,  const float* __restrict__ b2,
            const int*   __restrict__ ei,  float* __restrict__ out) {
    float* W1s = sm;                       // [INP][HID]
    float* W2s = sm + INP * HID;           // [HID][HID]
    float* A   = W2s + HID * HID;          // [INP][STRA], reused as H[HID][STRA]
    int*  dstS = (int*)(A + INP * STRA);   // [TILE]

    const int tid = threadIdx.x;
    const int tx = tid & 15;               // output group
    const int ty = tid >> 4;               // edge group (0..7): edges ty*8..ty*8+7

    // ---- load weights into SMEM once (persistent blocks) ----
    {
        const float4* g1 = (const float4*)W1;
        float4* s1 = (float4*)W1s;
        for (int i = tid; i < (195 * HID) / 4; i += NTHREADS) s1[i] = g1[i];
        float4 z4 = make_float4(0.f, 0.f, 0.f, 0.f);
        for (int i = tid; i < HID / 4; i += NTHREADS)
            ((float4*)(W1s + 195 * HID))[i] = z4;       // padded row 195 = 0
        const float4* g2 = (const float4*)W2;
        float4* s2 = (float4*)W2s;
        for (int i = tid; i < (HID * HID) / 4; i += NTHREADS) s2[i] = g2[i];
    }

    // bias pairs for this thread's 8 outputs: j<4 -> out=tx*4+j ; j>=4 -> out=64+tx*4+(j-4)
    u64 b1p[8], b2p[8];
    #pragma unroll
    for (int j = 0; j < 8; j++) {
        int o = (j < 4) ? (tx * 4 + j) : (64 + tx * 4 + (j - 4));
        float v1 = b1[o], v2 = b2[o];
        PACK2(b1p[j], v1);
        PACK2(b2p[j], v2);
    }

    const int e = tid & 63;                // builder edge (0..63)
    const int p = tid >> 6;                // builder role (0 or 1) — warp-uniform

    const float* Acol = A + ty * 8;

    for (int tile = blockIdx.x; tile < NT; tile += gridDim.x) {
        __syncthreads();   // protect A/H + dstS reuse across tiles

        // ---- build message-input tile A[196][64] ----
        {
            int ge = tile * TILE + e;
            bool valid = ge < NE;
            int src = valid ? ei[ge] : 0;
            int dst = valid ? ei[NE + ge] : 0;
            if (p == 0) {                  // rows 0..63: h_s[src]; rows 64..127: h_s[dst]
                const float4* rs = (const float4*)(h_s + (size_t)src * SD);
                const float4* rd = (const float4*)(h_s + (size_t)dst * SD);
                #pragma unroll
                for (int j = 0; j < 16; j++) {
                    float4 v = rs[j];
                    A[(4*j+0)*STRA + e] = v.x;
                    A[(4*j+1)*STRA + e] = v.y;
                    A[(4*j+2)*STRA + e] = v.z;
                    A[(4*j+3)*STRA + e] = v.w;
                }
                #pragma unroll
                for (int j = 0; j < 16; j++) {
                    float4 v = rd[j];
                    A[(64+4*j+0)*STRA + e] = v.x;
                    A[(64+4*j+1)*STRA + e] = v.y;
                    A[(64+4*j+2)*STRA + e] = v.z;
                    A[(64+4*j+3)*STRA + e] = v.w;
                }
            } else {                       // rows 128..191: rotated h_v[src]; 192..195 geo
                float alpha = orient[dst];
                float beta  = orient[src];
                float c, s_;
                sincosf(2.f * (beta - alpha), &s_, &c);
                const float4* r = (const float4*)(h_v + (size_t)src * VD);
                #pragma unroll
                for (int j = 0; j < 16; j++) {
                    float4 v = r[j];
                    A[(128+4*j+0)*STRA + e] = v.x * c - v.y * s_;
                    A[(128+4*j+1)*STRA + e] = v.x * s_ + v.y * c;
                    A[(128+4*j+2)*STRA + e] = v.z * c - v.w * s_;
                    A[(128+4*j+3)*STRA + e] = v.z * s_ + v.w * c;
                }
                float2 ps = ((const float2*)pos)[src];
                float2 pd = ((const float2*)pos)[dst];
                float dx = ps.x - pd.x, dy = ps.y - pd.y;
                float dist = sqrtf(dx * dx + dy * dy) + 1e-6f;
                float dphi = atan2f(dy, dx) - alpha;
                float c2, s2;
                sincosf(2.f * dphi, &s2, &c2);
                A[192*STRA + e] = dist;
                A[193*STRA + e] = c2;
                A[194*STRA + e] = s2;
                A[195*STRA + e] = 0.f;
                dstS[e] = valid ? dst : -1;
            }
        }
        __syncthreads();

        // ---- layer 1: H = silu(A^T @ W1 + b1), f32x2-packed over edge pairs ----
        u64 acc[8][4];
        #pragma unroll
        for (int j = 0; j < 8; j++)
            #pragma unroll
            for (int q = 0; q < 4; q++) acc[j][q] = b1p[j];

        #pragma unroll 2
        for (int k = 0; k < INP; k++) {
            ulonglong2 a01 = *(const ulonglong2*)(Acol + k * STRA);      // edges 0..3 (2 pairs)
            ulonglong2 a23 = *(const ulonglong2*)(Acol + k * STRA + 4);  // edges 4..7
            float4 wlo = *(const float4*)(W1s + k * HID + tx * 4);       // conflict-free, contiguous
            float4 whi = *(const float4*)(W1s + k * HID + 64 + tx * 4);
            u64 av[4] = {a01.x, a01.y, a23.x, a23.y};
            u64 wd[8];
            PACK2(wd[0], wlo.x); PACK2(wd[1], wlo.y); PACK2(wd[2], wlo.z); PACK2(wd[3], wlo.w);
            PACK2(wd[4], whi.x); PACK2(wd[5], whi.y); PACK2(wd[6], whi.z); PACK2(wd[7], whi.w);
            #pragma unroll
            for (int j = 0; j < 8; j++)
                #pragma unroll
                for (int q = 0; q < 4; q++)
                    FMA2(acc[j][q], av[q], wd[j]);
        }
        __syncthreads();   // all reads of A done before H overwrites it

        // ---- SiLU + store H[out][e] into A's buffer ----
        #pragma unroll
        for (int j = 0; j < 8; j++) {
            int o = (j < 4) ? (tx * 4 + j) : (64 + tx * 4 + (j - 4));
            #pragma unroll
            for (int q = 0; q < 4; q++) {
                float lo, hi;
                UNPACK2(lo, hi, acc[j][q]);
                lo = silu(lo); hi = silu(hi);
                PACK2(acc[j][q], lo);                  // reuse as temp: pack lo,hi
                asm("mov.b64 %0, {%1, %2};" : "=l"(acc[j][q]) : "f"(lo), "f"(hi));
            }
            *(ulonglong2*)(A + o * STRA + ty * 8)     = make_ulonglong2(acc[j][0], acc[j][1]);
            *(ulonglong2*)(A + o * STRA + ty * 8 + 4) = make_ulonglong2(acc[j][2], acc[j][3]);
        }
        __syncthreads();

        // ---- layer 2: M = H^T @ W2 + b2 ----
        u64 acc2[8][4];
        #pragma unroll
        for (int j = 0; j < 8; j++)
            #pragma unroll
            for (int q = 0; q < 4; q++) acc2[j][q] = b2p[j];

        #pragma unroll 2
        for (int k = 0; k < HID; k++) {
            ulonglong2 a01 = *(const ulonglong2*)(Acol + k * STRA);
            ulonglong2 a23 = *(const ulonglong2*)(Acol + k * STRA + 4);
            float4 wlo = *(const float4*)(W2s + k * HID + tx * 4);
            float4 whi = *(const float4*)(W2s + k * HID + 64 + tx * 4);
            u64 av[4] = {a01.x, a01.y, a23.x, a23.y};
            u64 wd[8];
            PACK2(wd[0], wlo.x); PACK2(wd[1], wlo.y); PACK2(wd[2], wlo.z); PACK2(wd[3], wlo.w);
            PACK2(wd[4], whi.x); PACK2(wd[5], whi.y); PACK2(wd[6], whi.z); PACK2(wd[7], whi.w);
            #pragma unroll
            for (int j = 0; j < 8; j++)
                #pragma unroll
                for (int q = 0; q < 4; q++)
                    FMA2(acc2[j][q], av[q], wd[j]);
        }

        // ---- scatter-add ----
        // outputs j<4 -> msg_s cols tx*4..+3 ; j>=4 -> msg_v cols tx*4..+3
        const size_t outv_off = (size_t)NN * SD;
        #pragma unroll
        for (int q = 0; q < 4; q++) {
            float v0[8], v1[8];
            #pragma unroll
            for (int j = 0; j < 8; j++) UNPACK2(v0[j], v1[j], acc2[j][q]);
            int d0 = dstS[ty * 8 + 2 * q];
            int d1 = dstS[ty * 8 + 2 * q + 1];
            if (d0 >= 0) {
                float* bs = out + (size_t)d0 * SD + tx * 4;
                red_add_v4(bs, v0[0], v0[1], v0[2], v0[3]);
                float* bv = out + outv_off + (size_t)d0 * VD + tx * 4;
                red_add_v4(bv, v0[4], v0[5], v0[6], v0[7]);
            }
            if (d1 >= 0) {
                float* bs = out + (size_t)d1 * SD + tx * 4;
                red_add_v4(bs, v1[0], v1[1], v1[2], v1[3]);
                float* bv = out + outv_off + (size_t)d1 * VD + tx * 4;
                red_add_v4(bv, v1[4], v1[5], v1[6], v1[7]);
            }
        }
    }
}

extern "C" void kernel_launch(void* const* d_in, const int* in_sizes, int n_in,
                              void* d_out, int out_size) {
    const float* h_s    = (const float*)d_in[0];
    const float* h_v    = (const float*)d_in[1];
    const float* pos    = (const float*)d_in[2];
    const float* orient = (const float*)d_in[3];
    const float* W1     = (const float*)d_in[4];
    const float* b1     = (const float*)d_in[5];
    const float* W2     = (const float*)d_in[6];
    const float* b2     = (const float*)d_in[7];
    const int*   ei     = (const int*)d_in[8];
    float* out = (float*)d_out;

    (void)in_sizes; (void)n_in; (void)out_size;

    int n4 = NN * SD / 4;
    init_out_kernel<<<(n4 + 255) / 256, 256>>>(h_s, h_v, out);

    cudaFuncSetAttribute(edge_kernel,
                         cudaFuncAttributeMaxDynamicSharedMemorySize, SMEM_BYTES);
    int nsm = 148;
    cudaDeviceGetAttribute(&nsm, cudaDevAttrMultiProcessorCount, 0);
    edge_kernel<<<nsm, NTHREADS, SMEM_BYTES>>>(h_s, h_v, pos, orient,
                                               W1, b1, W2, b2, ei, out);
}